// round 12
// baseline (speedup 1.0000x reference)
#include <cuda_runtime.h>
#include <math.h>

// Problem constants
#define NSYS 4096      // tridiagonal system size (= NX)
#define NT   4096      // time steps
#define ROWP 4104      // padded row stride
#define NTH  256       // threads in persistent kernel
#define NWARP 8
#define NDEN 256       // first NDEN Thomas rows stored exactly; rest converged

// Globals (no cudaMalloc allowed)
__device__ float g_par[8];            // [2] = tscale for k_interp
__device__ float g_U[(size_t)(NT + 1) * ROWP];

// ---------------------------------------------------------------------------
// Persistent single-CTA kernel, 256 threads x 16 elems, ONE barrier/step.
// Assembly of the individually-proven pieces (R9 + R10 + R11):
//   - SCALAR two independent 8-chains per thread (lo 0-7, hi 8-15) for ILP
//     (f32x2 packing measured slower 3x -- permanently rejected)
//   - carry algebra: gLf0*ex folded into the backward-scan input (ex-parts
//     of downstream carries ride the scan), WQ*C + WC*Cbc for the C-parts
//     (W1+W2-level accuracy, rel_err ~5e-5)
//   - exclusive scans ex/ex2 from TWO PARALLEL shuffles of the raw scan
//     inputs + precomputed MfEx/MbEx (one less serial shfl per half-step)
// ---------------------------------------------------------------------------
__global__ void __launch_bounds__(NTH, 1) k_main(
        const float* __restrict__ alpha, const float* __restrict__ vel,
        const float* __restrict__ r0p,   const float* __restrict__ r1p,
        const float* __restrict__ tq, int nq) {
    __shared__ float sF[2][NWARP], sD[2][NWARP];
    __shared__ float s_inlet[NT + 8];
    __shared__ unsigned char s_need[NT + 2];
    __shared__ float s_den[NDEN], s_cp[NDEN];
    __shared__ float sPar[8];
    __shared__ float smax[NWARP];

    int tid = threadIdx.x;
    int lane = tid & 31, wid = tid >> 5;
    int e0 = tid * 16;

    // ================= setup prologue =================
    for (int i = tid; i < NT + 2; i += NTH) s_need[i] = 0;

    float mx = -1e30f;
    for (int i = tid; i < nq; i += NTH) mx = fmaxf(mx, tq[i]);
    #pragma unroll
    for (int s = 16; s > 0; s >>= 1) mx = fmaxf(mx, __shfl_xor_sync(0xffffffffu, mx, s));
    if (lane == 0) smax[wid] = mx;
    __syncthreads();

    if (tid == 0) {
        float tmax = smax[0];
        for (int i = 1; i < NWARP; i++) tmax = fmaxf(tmax, smax[i]);
        float dt = tmax / 4096.0f;
        float inv_dt = 1.0f / dt;
        float al = *alpha, ve = *vel, r0 = *r0p, r1 = *r1p;
        float r_diff = al * 10000.0f;     // alpha / dx^2
        float r_adv  = ve * 50.0f;        // vel / (2 dx)
        float aconst = r_diff + r_adv;
        float b_int  = -2.0f * r_diff - inv_dt - r1;
        float c_int  = r_diff - r_adv;
        float b_last = -aconst - inv_dt - r1;
        float tscale = 4096.0f / tmax;
        sPar[0] = dt; sPar[1] = inv_dt; sPar[2] = tscale;
        sPar[3] = aconst; sPar[4] = r0;
        g_par[2] = tscale;
        s_cp[0] = 0.0f; s_den[0] = 1.0f;
        float cp = 0.0f;
        for (int i = 1; i < NDEN; i++) {
            float den = b_int - aconst * cp;
            cp = c_int / den;
            s_den[i] = den; s_cp[i] = cp;
        }
        sPar[5] = b_int - aconst * cp;
        sPar[6] = cp;
        sPar[7] = b_last - aconst * cp;
    }
    __syncthreads();

    float dt = sPar[0], inv_dt = sPar[1], tscale = sPar[2];
    float aconst = sPar[3], r0 = sPar[4];
    float denc = sPar[5], cpc = sPar[6], den_last = sPar[7];

    const float twopi = 6.283185307179586f;
    for (int n = tid; n <= NT; n += NTH)
        s_inlet[n] = 1.0f + 0.5f * sinf(twopi * ((float)n * dt));
    for (int i = tid; i < nq; i += NTH) {
        float tn = tq[i] * tscale;
        int i0 = (int)floorf(tn);
        i0 = max(0, min(i0, NT - 1));
        s_need[i0] = 1;
        s_need[i0 + 1] = 1;
    }

    // ================= per-thread constants =================
    float av[16], cv[16], f1s[16], f0s[16];
    float gl[16], Lb[16];       // per-BLOCK gL and Lb (lo: 0-7, hi: 8-15)
    float A8lo, A8hi, B8lo, B8hi, gH0, A, Bfull, gLf0;
    {
        #pragma unroll
        for (int k = 0; k < 16; k++) {
            int e = e0 + k;
            float den = (e < NDEN) ? s_den[e] : denc;
            float cp  = (e < NDEN) ? s_cp[e]  : cpc;
            if (e == NSYS - 1) { den = den_last; cp = 0.0f; }
            float rc = 1.0f / den;
            av[k] = (e == 0) ? 0.0f : (-aconst * rc);
            cv[k] = -cp;
            f1s[k] = -inv_dt * rc;
            f0s[k] = r0 * (0.01f * (float)e) * rc;
        }
        float Lf[16];
        Lf[0] = av[0];  Lf[8] = av[8];
        #pragma unroll
        for (int k = 1; k < 8; k++) {
            Lf[k]     = Lf[k - 1] * av[k];
            Lf[8 + k] = Lf[7 + k] * av[8 + k];
        }
        Lb[7] = cv[7];  Lb[15] = cv[15];
        #pragma unroll
        for (int k = 6; k >= 0; k--) {
            Lb[k]     = cv[k]     * Lb[k + 1];
            Lb[8 + k] = cv[8 + k] * Lb[9 + k];
        }
        gl[7] = Lf[7]; gl[15] = Lf[15];
        #pragma unroll
        for (int k = 6; k >= 0; k--) {
            gl[k]     = fmaf(cv[k],     gl[k + 1], Lf[k]);
            gl[8 + k] = fmaf(cv[8 + k], gl[9 + k], Lf[8 + k]);
        }
        A8lo = Lf[7]; A8hi = Lf[15];
        B8lo = Lb[0]; B8hi = Lb[8];
        gH0 = gl[8];
        A = A8lo * A8hi;
        Bfull = B8lo * B8hi;
        gLf0 = fmaf(B8lo * A8lo, gH0, gl[0]);    // full-16 gL[0]
    }

    // ---- warp-scan constants ----
    float v;
    float Mf0 = (lane >= 1) ? A : 0.0f;
    float MfEx = __shfl_up_sync(0xffffffffu, Mf0, 1); if (lane == 0) MfEx = 0.0f;
    float Aa = A;
    v = __shfl_up_sync(0xffffffffu, Aa, 1);  if (lane >= 1)  Aa *= v;
    v = __shfl_up_sync(0xffffffffu, Aa, 2);  if (lane >= 2)  Aa *= v;
    v = __shfl_up_sync(0xffffffffu, Aa, 4);  if (lane >= 4)  Aa *= v;
    v = __shfl_up_sync(0xffffffffu, Aa, 8);  if (lane >= 8)  Aa *= v;
    v = __shfl_up_sync(0xffffffffu, Aa, 16); if (lane >= 16) Aa *= v;
    float Qf = __shfl_up_sync(0xffffffffu, Aa, 1); if (lane == 0) Qf = 1.0f;

    float Mb0 = (lane <= 30) ? Bfull : 0.0f;
    float MbEx = __shfl_down_sync(0xffffffffu, Mb0, 1); if (lane == 31) MbEx = 0.0f;
    float Bb = Bfull;
    v = __shfl_down_sync(0xffffffffu, Bb, 1);  if (lane <= 30) Bb *= v;
    v = __shfl_down_sync(0xffffffffu, Bb, 2);  if (lane <= 29) Bb *= v;
    v = __shfl_down_sync(0xffffffffu, Bb, 4);  if (lane <= 27) Bb *= v;
    v = __shfl_down_sync(0xffffffffu, Bb, 8);  if (lane <= 23) Bb *= v;
    v = __shfl_down_sync(0xffffffffu, Bb, 16); if (lane <= 15) Bb *= v;
    float Qb = __shfl_down_sync(0xffffffffu, Bb, 1); if (lane == 31) Qb = 1.0f;

    // ---- step-invariant carry-correction weights (R10 set, proven 5e-5) ----
    float Zq = gLf0 * Qf;
    float WQ = __shfl_down_sync(0xffffffffu, Zq, 1);
    if (lane == 31) WQ = 0.0f;           // t+1 crosses the warp -> handled by WC
    float WC = 0.0f;
    {
        float avc = -aconst / denc;
        float cvc = -cpc;
        float Lfk[16];
        #pragma unroll
        for (int k = 0; k < 16; k++) Lfk[k] = (k == 0) ? avc : Lfk[k - 1] * avc;
        float glc = Lfk[15];
        #pragma unroll
        for (int k = 14; k >= 0; k--) glc = fmaf(cvc, glc, Lfk[k]);
        float Bnext1 = __shfl_down_sync(0xffffffffu, Bfull, 1);
        if (wid < NWARP - 1) {
            if (lane == 31)      WC = glc;            // j=1 crossing
            else if (lane == 30) WC = Bnext1 * glc;   // j=2 crossing
        }
    }

    // ================= initial state: u = 1, row 0 =================
    float m[16];
    #pragma unroll
    for (int k = 0; k < 16; k++) m[k] = 1.0f;
    {
        float4 one4 = make_float4(1.f, 1.f, 1.f, 1.f);
        float4* p = (float4*)(g_U + e0);
        p[0] = one4; p[1] = one4; p[2] = one4; p[3] = one4;
        if (tid == NTH - 1) g_U[NSYS] = 1.0f;
    }
    __syncthreads();

    // ================= time loop =================
    float* row = g_U + ROWP + e0;
    float inl = s_inlet[1];
    for (int n = 0; n < NT; n++) {
        int par = n & 1;

        // ---- rhs + two independent forward chains (zero block carries) ----
        float b0 = fmaf(m[0], f1s[0], f0s[0]);
        m[0] = (tid == 0) ? inl : b0;
        m[8] = fmaf(m[8], f1s[8], f0s[8]);
        #pragma unroll
        for (int k = 1; k < 8; k++) {
            m[k]     = fmaf(av[k],     m[k - 1], fmaf(m[k],     f1s[k],     f0s[k]));
            m[8 + k] = fmaf(av[8 + k], m[7 + k], fmaf(m[8 + k], f1s[8 + k], f0s[8 + k]));
        }
        float P8lo = m[7];
        float P = fmaf(A8hi, P8lo, m[15]);    // exact thread-level local sum

        // ---- forward exclusive scan via 2 PARALLEL shuffles ----
        float pr1 = __shfl_up_sync(0xffffffffu, P, 1);
        float pr2 = __shfl_up_sync(0xffffffffu, P, 2);
        float ex = (lane == 0) ? 0.0f : fmaf(MfEx, pr2, pr1);
        float Psc = fmaf(Mf0, pr1, P);        // scanned P
        if (lane == 31) sF[par][wid] = Psc;
        float Cbc = __shfl_sync(0xffffffffu, Psc, 31);  // own warp total
        float WCc = WC * Cbc;                 // off the critical path

        // ---- two independent backward chains (zero block carries) ----
        #pragma unroll
        for (int k = 6; k >= 0; k--) {
            m[k]     = fmaf(cv[k],     m[k + 1], m[k]);
            m[8 + k] = fmaf(cv[8 + k], m[9 + k], m[8 + k]);
        }
        float Glo = m[0], Ghi = m[8];
        // scan input = gm0_full + gLf0*ex  (ex-parts of downstream carries)
        float P2 = fmaf(B8lo, fmaf(P8lo, gH0, Ghi), Glo);
        P2 = fmaf(gLf0, ex, P2);

        // ---- backward exclusive scan via 2 PARALLEL shuffles ----
        float qd1 = __shfl_down_sync(0xffffffffu, P2, 1);
        float qd2 = __shfl_down_sync(0xffffffffu, P2, 2);
        float ex2 = (lane == 31) ? 0.0f : fmaf(MbEx, qd2, qd1);
        if (lane == 0) sD[par][wid] = fmaf(Mb0, qd1, P2);  // scanned P2

        float inl_nx = s_inlet[n + 2];
        bool need = s_need[n + 1] != 0;
        __syncthreads();

        // ---- post-barrier: carries (depth-2 tree from the LDS) ----
        float C  = (wid > 0) ? sF[par][wid - 1] : 0.0f;
        float Dm = (wid < NWARP - 1) ? sD[par][wid + 1] : 0.0f;
        float c  = fmaf(Qf, C, ex);
        float T1 = fmaf(Qb, Dm, ex2);
        float T2 = fmaf(WQ, C, WCc);
        float S  = T1 + T2;

        // ---- exact block carries + apply (two independent streams) ----
        float cbh = fmaf(A8lo, c, P8lo);                    // fwd carry into hi
        float Sbl = fmaf(B8hi, S, fmaf(cbh, gH0, Ghi));     // back carry into lo
        #pragma unroll
        for (int k = 0; k < 8; k++) {
            m[k]     = fmaf(Lb[k],     Sbl, fmaf(c,   gl[k],     m[k]));
            m[8 + k] = fmaf(Lb[8 + k], S,   fmaf(cbh, gl[8 + k], m[8 + k]));
        }

        // ---- store row n+1 only if the interpolation will read it ----
        if (need) {
            float4* p = (float4*)row;
            p[0] = make_float4(m[0],  m[1],  m[2],  m[3]);
            p[1] = make_float4(m[4],  m[5],  m[6],  m[7]);
            p[2] = make_float4(m[8],  m[9],  m[10], m[11]);
            p[3] = make_float4(m[12], m[13], m[14], m[15]);
            if (tid == NTH - 1) row[NSYS - e0] = m[15];  // Neumann outlet copy
        }
        row += ROWP;
        inl = inl_nx;
    }
}

// ---------------------------------------------------------------------------
// Interpolation:  out[b] = (1-w) U[idx0] + w U[idx1]
// ---------------------------------------------------------------------------
__global__ void k_interp(const float* __restrict__ tq, float* __restrict__ out) {
    int b = blockIdx.x;
    float tn = tq[b] * g_par[2];
    float f = floorf(tn);
    int i0 = (int)f;
    i0 = max(0, min(i0, NT - 1));
    float w = tn - (float)i0;
    const float* r0 = g_U + (size_t)i0 * ROWP;
    const float* r1 = r0 + ROWP;
    float* o = out + (size_t)b * (NSYS + 1);
    for (int x = threadIdx.x; x <= NSYS; x += blockDim.x)
        o[x] = (1.0f - w) * r0[x] + w * r1[x];
}

// ---------------------------------------------------------------------------
extern "C" void kernel_launch(void* const* d_in, const int* in_sizes, int n_in,
                              void* d_out, int out_size) {
    const float* alpha = (const float*)d_in[0];
    const float* vel   = (const float*)d_in[1];
    const float* r0    = (const float*)d_in[2];
    const float* r1    = (const float*)d_in[3];
    const float* t     = (const float*)d_in[4];
    int B = in_sizes[4];

    k_main<<<1, NTH>>>(alpha, vel, r0, r1, t, B);
    k_interp<<<B, 256>>>(t, (float*)d_out);
}

// round 14
// speedup vs baseline: 1.1682x; 1.1682x over previous
#include <cuda_runtime.h>
#include <math.h>

// Problem constants
#define NSYS 4096      // tridiagonal system size (= NX)
#define NT   4096      // time steps
#define ROWP 4104      // padded row stride
#define NTH  256       // threads in persistent kernel
#define NWARP 8
#define NDEN 256       // first NDEN Thomas rows stored exactly; rest converged

// Globals (no cudaMalloc allowed)
__device__ float g_par[8];            // [2] = tscale for k_interp
__device__ float g_U[(size_t)(NT + 1) * ROWP];

// ---------------------------------------------------------------------------
// Persistent single-CTA kernel, 256 threads x 16 elems, ONE barrier/step.
// Measured-best configuration (R9, 1497 us):
//   - two INDEPENDENT scalar 8-chains per thread (lo 0-7, hi 8-15) with
//     exact block merges (P = A8hi*P8lo + m15; cbh = A8lo*c + P8lo;
//     Sbl = B8hi*S + cbh*gH0 + Ghi) for 2-way ILP in the FMA chains
//   - 1-round truncated warp scans (per-thread A ~ 8e-7)
//   - W1 cross-thread carry term only; rel_err 5.46e-4 deterministic
//     (fixed-seed inputs), margin 1.8x under the 1e-3 gate
//   - ping-pong smem carry buffers; rows not read by the interpolation
//     are not stored
// ---------------------------------------------------------------------------
__global__ void __launch_bounds__(NTH, 1) k_main(
        const float* __restrict__ alpha, const float* __restrict__ vel,
        const float* __restrict__ r0p,   const float* __restrict__ r1p,
        const float* __restrict__ tq, int nq) {
    __shared__ float sF[2][NWARP], sD[2][NWARP];
    __shared__ float s_inlet[NT + 8];
    __shared__ unsigned char s_need[NT + 2];
    __shared__ float s_den[NDEN], s_cp[NDEN];
    __shared__ float sPar[8];
    __shared__ float smax[NWARP];

    int tid = threadIdx.x;
    int lane = tid & 31, wid = tid >> 5;
    int e0 = tid * 16;

    // ================= setup prologue =================
    for (int i = tid; i < NT + 2; i += NTH) s_need[i] = 0;

    float mx = -1e30f;
    for (int i = tid; i < nq; i += NTH) mx = fmaxf(mx, tq[i]);
    #pragma unroll
    for (int s = 16; s > 0; s >>= 1) mx = fmaxf(mx, __shfl_xor_sync(0xffffffffu, mx, s));
    if (lane == 0) smax[wid] = mx;
    __syncthreads();

    if (tid == 0) {
        float tmax = smax[0];
        for (int i = 1; i < NWARP; i++) tmax = fmaxf(tmax, smax[i]);
        float dt = tmax / 4096.0f;
        float inv_dt = 1.0f / dt;
        float al = *alpha, ve = *vel, r0 = *r0p, r1 = *r1p;
        float r_diff = al * 10000.0f;     // alpha / dx^2
        float r_adv  = ve * 50.0f;        // vel / (2 dx)
        float aconst = r_diff + r_adv;
        float b_int  = -2.0f * r_diff - inv_dt - r1;
        float c_int  = r_diff - r_adv;
        float b_last = -aconst - inv_dt - r1;
        float tscale = 4096.0f / tmax;
        sPar[0] = dt; sPar[1] = inv_dt; sPar[2] = tscale;
        sPar[3] = aconst; sPar[4] = r0;
        g_par[2] = tscale;
        s_cp[0] = 0.0f; s_den[0] = 1.0f;
        float cp = 0.0f;
        for (int i = 1; i < NDEN; i++) {
            float den = b_int - aconst * cp;
            cp = c_int / den;
            s_den[i] = den; s_cp[i] = cp;
        }
        sPar[5] = b_int - aconst * cp;
        sPar[6] = cp;
        sPar[7] = b_last - aconst * cp;
    }
    __syncthreads();

    float dt = sPar[0], inv_dt = sPar[1], tscale = sPar[2];
    float aconst = sPar[3], r0 = sPar[4];
    float denc = sPar[5], cpc = sPar[6], den_last = sPar[7];

    const float twopi = 6.283185307179586f;
    for (int n = tid; n <= NT; n += NTH)
        s_inlet[n] = 1.0f + 0.5f * sinf(twopi * ((float)n * dt));
    for (int i = tid; i < nq; i += NTH) {
        float tn = tq[i] * tscale;
        int i0 = (int)floorf(tn);
        i0 = max(0, min(i0, NT - 1));
        s_need[i0] = 1;
        s_need[i0 + 1] = 1;
    }

    // ================= per-thread constants =================
    float av[16], cv[16], f1s[16], f0s[16];
    float gl[16], Lb[16];       // per-BLOCK gL and Lb (lo: 0-7, hi: 8-15)
    float A8lo, A8hi, B8lo, B8hi, gH0, A, Bfull, gLf0;
    {
        #pragma unroll
        for (int k = 0; k < 16; k++) {
            int e = e0 + k;
            float den = (e < NDEN) ? s_den[e] : denc;
            float cp  = (e < NDEN) ? s_cp[e]  : cpc;
            if (e == NSYS - 1) { den = den_last; cp = 0.0f; }
            float rc = 1.0f / den;
            av[k] = (e == 0) ? 0.0f : (-aconst * rc);
            cv[k] = -cp;
            f1s[k] = -inv_dt * rc;
            f0s[k] = r0 * (0.01f * (float)e) * rc;
        }
        float Lf[16];
        Lf[0] = av[0];  Lf[8] = av[8];
        #pragma unroll
        for (int k = 1; k < 8; k++) {
            Lf[k]     = Lf[k - 1] * av[k];
            Lf[8 + k] = Lf[7 + k] * av[8 + k];
        }
        Lb[7] = cv[7];  Lb[15] = cv[15];
        #pragma unroll
        for (int k = 6; k >= 0; k--) {
            Lb[k]     = cv[k]     * Lb[k + 1];
            Lb[8 + k] = cv[8 + k] * Lb[9 + k];
        }
        gl[7] = Lf[7]; gl[15] = Lf[15];
        #pragma unroll
        for (int k = 6; k >= 0; k--) {
            gl[k]     = fmaf(cv[k],     gl[k + 1], Lf[k]);
            gl[8 + k] = fmaf(cv[8 + k], gl[9 + k], Lf[8 + k]);
        }
        A8lo = Lf[7]; A8hi = Lf[15];
        B8lo = Lb[0]; B8hi = Lb[8];
        gH0 = gl[8];
        A = A8lo * A8hi;
        Bfull = B8lo * B8hi;
        gLf0 = fmaf(B8lo * A8lo, gH0, gl[0]);    // full-16 gL[0]
    }

    // ---- warp-scan constants (R5/R9 set: 1-round scans, W1 only) ----
    float v;
    float Mf0 = (lane >= 1) ? A : 0.0f;
    float Aa = A;
    v = __shfl_up_sync(0xffffffffu, Aa, 1);  if (lane >= 1)  Aa *= v;
    v = __shfl_up_sync(0xffffffffu, Aa, 2);  if (lane >= 2)  Aa *= v;
    v = __shfl_up_sync(0xffffffffu, Aa, 4);  if (lane >= 4)  Aa *= v;
    v = __shfl_up_sync(0xffffffffu, Aa, 8);  if (lane >= 8)  Aa *= v;
    v = __shfl_up_sync(0xffffffffu, Aa, 16); if (lane >= 16) Aa *= v;
    float Qf = __shfl_up_sync(0xffffffffu, Aa, 1); if (lane == 0) Qf = 1.0f;
    float QfD1 = __shfl_down_sync(0xffffffffu, Qf, 1);
    if (lane == 31) QfD1 = 0.0f;               // lane31: cn1 = own P

    float Mb0 = (lane <= 30) ? Bfull : 0.0f;
    float Bb = Bfull;
    v = __shfl_down_sync(0xffffffffu, Bb, 1);  if (lane <= 30) Bb *= v;
    v = __shfl_down_sync(0xffffffffu, Bb, 2);  if (lane <= 29) Bb *= v;
    v = __shfl_down_sync(0xffffffffu, Bb, 4);  if (lane <= 27) Bb *= v;
    v = __shfl_down_sync(0xffffffffu, Bb, 8);  if (lane <= 23) Bb *= v;
    v = __shfl_down_sync(0xffffffffu, Bb, 16); if (lane <= 15) Bb *= v;
    float Qb = __shfl_down_sync(0xffffffffu, Bb, 1); if (lane == 31) Qb = 1.0f;

    // cross-thread carry weight: W1 = gL0 of thread t+1
    float W1 = __shfl_down_sync(0xffffffffu, gLf0, 1);
    if (tid == NTH - 1) W1 = 0.0f;

    // ================= initial state: u = 1, row 0 =================
    float m[16];
    #pragma unroll
    for (int k = 0; k < 16; k++) m[k] = 1.0f;
    {
        float4 one4 = make_float4(1.f, 1.f, 1.f, 1.f);
        float4* p = (float4*)(g_U + e0);
        p[0] = one4; p[1] = one4; p[2] = one4; p[3] = one4;
        if (tid == NTH - 1) g_U[NSYS] = 1.0f;
    }
    __syncthreads();

    // ================= time loop =================
    float* row = g_U + ROWP + e0;
    float inl = s_inlet[1];
    for (int n = 0; n < NT; n++) {
        int par = n & 1;

        // ---- rhs + two independent forward chains (zero block carries) ----
        float b0 = fmaf(m[0], f1s[0], f0s[0]);
        m[0] = (tid == 0) ? inl : b0;
        m[8] = fmaf(m[8], f1s[8], f0s[8]);
        #pragma unroll
        for (int k = 1; k < 8; k++) {
            m[k]     = fmaf(av[k],     m[k - 1], fmaf(m[k],     f1s[k],     f0s[k]));
            m[8 + k] = fmaf(av[8 + k], m[7 + k], fmaf(m[8 + k], f1s[8 + k], f0s[8 + k]));
        }
        float P8lo = m[7];
        float P = fmaf(A8hi, P8lo, m[15]);    // exact thread-level local sum

        // ---- forward warp scan (1 round) ----
        v = __shfl_up_sync(0xffffffffu, P, 1); P = fmaf(Mf0, v, P);
        float ex = __shfl_up_sync(0xffffffffu, P, 1); if (lane == 0) ex = 0.0f;
        if (lane == 31) sF[par][wid] = P;

        // ---- two independent backward chains (zero block carries) ----
        #pragma unroll
        for (int k = 6; k >= 0; k--) {
            m[k]     = fmaf(cv[k],     m[k + 1], m[k]);
            m[8 + k] = fmaf(cv[8 + k], m[9 + k], m[8 + k]);
        }
        float Glo = m[0], Ghi = m[8];
        float P2 = fmaf(B8lo, fmaf(P8lo, gH0, Ghi), Glo);  // exact thread gm[0]

        // ---- backward warp scan (1 round), PRE-barrier ----
        v = __shfl_down_sync(0xffffffffu, P2, 1); P2 = fmaf(Mb0, v, P2);
        float ex2 = __shfl_down_sync(0xffffffffu, P2, 1); if (lane == 31) ex2 = 0.0f;
        if (lane == 0) sD[par][wid] = P2;

        float inl_nx = s_inlet[n + 2];
        bool need = s_need[n + 1] != 0;
        __syncthreads();

        // ---- post-barrier: R9 carry algebra ----
        float C  = (wid > 0) ? sF[par][wid - 1] : 0.0f;
        float Dm = (wid < NWARP - 1) ? sD[par][wid + 1] : 0.0f;
        float c   = fmaf(Qf,   C, ex);
        float cn1 = fmaf(QfD1, C, P);             // carry of thread t+1
        float Sa  = fmaf(Qb, Dm, ex2);
        float S   = fmaf(W1, cn1, Sa);

        // ---- exact block carries + apply (two independent streams) ----
        float cbh = fmaf(A8lo, c, P8lo);                    // fwd carry into hi
        float Sbl = fmaf(B8hi, S, fmaf(cbh, gH0, Ghi));     // back carry into lo
        #pragma unroll
        for (int k = 0; k < 8; k++) {
            m[k]     = fmaf(Lb[k],     Sbl, fmaf(c,   gl[k],     m[k]));
            m[8 + k] = fmaf(Lb[8 + k], S,   fmaf(cbh, gl[8 + k], m[8 + k]));
        }

        // ---- store row n+1 only if the interpolation will read it ----
        if (need) {
            float4* p = (float4*)row;
            p[0] = make_float4(m[0],  m[1],  m[2],  m[3]);
            p[1] = make_float4(m[4],  m[5],  m[6],  m[7]);
            p[2] = make_float4(m[8],  m[9],  m[10], m[11]);
            p[3] = make_float4(m[12], m[13], m[14], m[15]);
            if (tid == NTH - 1) row[NSYS - e0] = m[15];  // Neumann outlet copy
        }
        row += ROWP;
        inl = inl_nx;
    }
}

// ---------------------------------------------------------------------------
// Interpolation:  out[b] = (1-w) U[idx0] + w U[idx1]
// ---------------------------------------------------------------------------
__global__ void k_interp(const float* __restrict__ tq, float* __restrict__ out) {
    int b = blockIdx.x;
    float tn = tq[b] * g_par[2];
    float f = floorf(tn);
    int i0 = (int)f;
    i0 = max(0, min(i0, NT - 1));
    float w = tn - (float)i0;
    const float* r0 = g_U + (size_t)i0 * ROWP;
    const float* r1 = r0 + ROWP;
    float* o = out + (size_t)b * (NSYS + 1);
    for (int x = threadIdx.x; x <= NSYS; x += blockDim.x)
        o[x] = (1.0f - w) * r0[x] + w * r1[x];
}

// ---------------------------------------------------------------------------
extern "C" void kernel_launch(void* const* d_in, const int* in_sizes, int n_in,
                              void* d_out, int out_size) {
    const float* alpha = (const float*)d_in[0];
    const float* vel   = (const float*)d_in[1];
    const float* r0    = (const float*)d_in[2];
    const float* r1    = (const float*)d_in[3];
    const float* t     = (const float*)d_in[4];
    int B = in_sizes[4];

    k_main<<<1, NTH>>>(alpha, vel, r0, r1, t, B);
    k_interp<<<B, 256>>>(t, (float*)d_out);
}

// round 15
// speedup vs baseline: 1.1957x; 1.0235x over previous
#include <cuda_runtime.h>
#include <math.h>

// Problem constants
#define NSYS 4096      // tridiagonal system size (= NX)
#define NT   4096      // time steps
#define ROWP 4104      // padded row stride
#define NTH  256       // threads in persistent kernel
#define NWARP 8
#define NDEN 256       // first NDEN Thomas rows stored exactly; rest converged

// Globals (no cudaMalloc allowed)
__device__ float g_par[8];            // [2] = tscale for k_interp
__device__ float g_U[(size_t)(NT + 1) * ROWP];

// ---------------------------------------------------------------------------
// Persistent single-CTA kernel, 256 threads x 16 elems, ONE barrier/step.
// = R9 (measured best, reproduced 1497 us twice, rel_err 5.4586e-4
//   deterministic) with ONE strict reduction: the two post-barrier scalar
//   LDS (sF[wid-1], sD[wid+1]) merged into a single 64-bit LDS via slot
//   co-location:  lane31 writes F_w -> Z[2w+4], lane0 writes D_w -> Z[2w+1],
//   reader wid loads the aligned pair Z[2wid+2..3] = (F_{wid-1}, D_{wid+1}).
//   Edge slots are unwritten garbage discarded by the existing predicates.
// Everything else (two independent scalar 8-chains, 1-round truncated warp
// scans, W1 carry term, ping-pong buffers, need-predicated stores) is
// bit-identical to R9.
// ---------------------------------------------------------------------------
__global__ void __launch_bounds__(NTH, 1) k_main(
        const float* __restrict__ alpha, const float* __restrict__ vel,
        const float* __restrict__ r0p,   const float* __restrict__ r1p,
        const float* __restrict__ tq, int nq) {
    __shared__ __align__(8) float sZ[2][20];   // carry-exchange slots
    __shared__ float s_inlet[NT + 8];
    __shared__ unsigned char s_need[NT + 2];
    __shared__ float s_den[NDEN], s_cp[NDEN];
    __shared__ float sPar[8];
    __shared__ float smax[NWARP];

    int tid = threadIdx.x;
    int lane = tid & 31, wid = tid >> 5;
    int e0 = tid * 16;

    // ================= setup prologue =================
    for (int i = tid; i < NT + 2; i += NTH) s_need[i] = 0;

    float mx = -1e30f;
    for (int i = tid; i < nq; i += NTH) mx = fmaxf(mx, tq[i]);
    #pragma unroll
    for (int s = 16; s > 0; s >>= 1) mx = fmaxf(mx, __shfl_xor_sync(0xffffffffu, mx, s));
    if (lane == 0) smax[wid] = mx;
    __syncthreads();

    if (tid == 0) {
        float tmax = smax[0];
        for (int i = 1; i < NWARP; i++) tmax = fmaxf(tmax, smax[i]);
        float dt = tmax / 4096.0f;
        float inv_dt = 1.0f / dt;
        float al = *alpha, ve = *vel, r0 = *r0p, r1 = *r1p;
        float r_diff = al * 10000.0f;     // alpha / dx^2
        float r_adv  = ve * 50.0f;        // vel / (2 dx)
        float aconst = r_diff + r_adv;
        float b_int  = -2.0f * r_diff - inv_dt - r1;
        float c_int  = r_diff - r_adv;
        float b_last = -aconst - inv_dt - r1;
        float tscale = 4096.0f / tmax;
        sPar[0] = dt; sPar[1] = inv_dt; sPar[2] = tscale;
        sPar[3] = aconst; sPar[4] = r0;
        g_par[2] = tscale;
        s_cp[0] = 0.0f; s_den[0] = 1.0f;
        float cp = 0.0f;
        for (int i = 1; i < NDEN; i++) {
            float den = b_int - aconst * cp;
            cp = c_int / den;
            s_den[i] = den; s_cp[i] = cp;
        }
        sPar[5] = b_int - aconst * cp;
        sPar[6] = cp;
        sPar[7] = b_last - aconst * cp;
        // zero the carry-exchange slots (edge slots stay benign)
        for (int i = 0; i < 20; i++) { sZ[0][i] = 0.0f; sZ[1][i] = 0.0f; }
    }
    __syncthreads();

    float dt = sPar[0], inv_dt = sPar[1], tscale = sPar[2];
    float aconst = sPar[3], r0 = sPar[4];
    float denc = sPar[5], cpc = sPar[6], den_last = sPar[7];

    const float twopi = 6.283185307179586f;
    for (int n = tid; n <= NT; n += NTH)
        s_inlet[n] = 1.0f + 0.5f * sinf(twopi * ((float)n * dt));
    for (int i = tid; i < nq; i += NTH) {
        float tn = tq[i] * tscale;
        int i0 = (int)floorf(tn);
        i0 = max(0, min(i0, NT - 1));
        s_need[i0] = 1;
        s_need[i0 + 1] = 1;
    }

    // ================= per-thread constants =================
    float av[16], cv[16], f1s[16], f0s[16];
    float gl[16], Lb[16];       // per-BLOCK gL and Lb (lo: 0-7, hi: 8-15)
    float A8lo, A8hi, B8lo, B8hi, gH0, A, Bfull, gLf0;
    {
        #pragma unroll
        for (int k = 0; k < 16; k++) {
            int e = e0 + k;
            float den = (e < NDEN) ? s_den[e] : denc;
            float cp  = (e < NDEN) ? s_cp[e]  : cpc;
            if (e == NSYS - 1) { den = den_last; cp = 0.0f; }
            float rc = 1.0f / den;
            av[k] = (e == 0) ? 0.0f : (-aconst * rc);
            cv[k] = -cp;
            f1s[k] = -inv_dt * rc;
            f0s[k] = r0 * (0.01f * (float)e) * rc;
        }
        float Lf[16];
        Lf[0] = av[0];  Lf[8] = av[8];
        #pragma unroll
        for (int k = 1; k < 8; k++) {
            Lf[k]     = Lf[k - 1] * av[k];
            Lf[8 + k] = Lf[7 + k] * av[8 + k];
        }
        Lb[7] = cv[7];  Lb[15] = cv[15];
        #pragma unroll
        for (int k = 6; k >= 0; k--) {
            Lb[k]     = cv[k]     * Lb[k + 1];
            Lb[8 + k] = cv[8 + k] * Lb[9 + k];
        }
        gl[7] = Lf[7]; gl[15] = Lf[15];
        #pragma unroll
        for (int k = 6; k >= 0; k--) {
            gl[k]     = fmaf(cv[k],     gl[k + 1], Lf[k]);
            gl[8 + k] = fmaf(cv[8 + k], gl[9 + k], Lf[8 + k]);
        }
        A8lo = Lf[7]; A8hi = Lf[15];
        B8lo = Lb[0]; B8hi = Lb[8];
        gH0 = gl[8];
        A = A8lo * A8hi;
        Bfull = B8lo * B8hi;
        gLf0 = fmaf(B8lo * A8lo, gH0, gl[0]);    // full-16 gL[0]
    }

    // ---- warp-scan constants (R9 set: 1-round scans, W1 only) ----
    float v;
    float Mf0 = (lane >= 1) ? A : 0.0f;
    float Aa = A;
    v = __shfl_up_sync(0xffffffffu, Aa, 1);  if (lane >= 1)  Aa *= v;
    v = __shfl_up_sync(0xffffffffu, Aa, 2);  if (lane >= 2)  Aa *= v;
    v = __shfl_up_sync(0xffffffffu, Aa, 4);  if (lane >= 4)  Aa *= v;
    v = __shfl_up_sync(0xffffffffu, Aa, 8);  if (lane >= 8)  Aa *= v;
    v = __shfl_up_sync(0xffffffffu, Aa, 16); if (lane >= 16) Aa *= v;
    float Qf = __shfl_up_sync(0xffffffffu, Aa, 1); if (lane == 0) Qf = 1.0f;
    float QfD1 = __shfl_down_sync(0xffffffffu, Qf, 1);
    if (lane == 31) QfD1 = 0.0f;               // lane31: cn1 = own P

    float Mb0 = (lane <= 30) ? Bfull : 0.0f;
    float Bb = Bfull;
    v = __shfl_down_sync(0xffffffffu, Bb, 1);  if (lane <= 30) Bb *= v;
    v = __shfl_down_sync(0xffffffffu, Bb, 2);  if (lane <= 29) Bb *= v;
    v = __shfl_down_sync(0xffffffffu, Bb, 4);  if (lane <= 27) Bb *= v;
    v = __shfl_down_sync(0xffffffffu, Bb, 8);  if (lane <= 23) Bb *= v;
    v = __shfl_down_sync(0xffffffffu, Bb, 16); if (lane <= 15) Bb *= v;
    float Qb = __shfl_down_sync(0xffffffffu, Bb, 1); if (lane == 31) Qb = 1.0f;

    // cross-thread carry weight: W1 = gL0 of thread t+1
    float W1 = __shfl_down_sync(0xffffffffu, gLf0, 1);
    if (tid == NTH - 1) W1 = 0.0f;

    // ================= initial state: u = 1, row 0 =================
    float m[16];
    #pragma unroll
    for (int k = 0; k < 16; k++) m[k] = 1.0f;
    {
        float4 one4 = make_float4(1.f, 1.f, 1.f, 1.f);
        float4* p = (float4*)(g_U + e0);
        p[0] = one4; p[1] = one4; p[2] = one4; p[3] = one4;
        if (tid == NTH - 1) g_U[NSYS] = 1.0f;
    }
    __syncthreads();

    // ================= time loop =================
    float* row = g_U + ROWP + e0;
    float inl = s_inlet[1];
    bool notfirst = (wid > 0);
    bool notlast  = (wid < NWARP - 1);
    for (int n = 0; n < NT; n++) {
        int par = n & 1;

        // ---- rhs + two independent forward chains (zero block carries) ----
        float b0 = fmaf(m[0], f1s[0], f0s[0]);
        m[0] = (tid == 0) ? inl : b0;
        m[8] = fmaf(m[8], f1s[8], f0s[8]);
        #pragma unroll
        for (int k = 1; k < 8; k++) {
            m[k]     = fmaf(av[k],     m[k - 1], fmaf(m[k],     f1s[k],     f0s[k]));
            m[8 + k] = fmaf(av[8 + k], m[7 + k], fmaf(m[8 + k], f1s[8 + k], f0s[8 + k]));
        }
        float P8lo = m[7];
        float P = fmaf(A8hi, P8lo, m[15]);    // exact thread-level local sum

        // ---- forward warp scan (1 round) ----
        v = __shfl_up_sync(0xffffffffu, P, 1); P = fmaf(Mf0, v, P);
        float ex = __shfl_up_sync(0xffffffffu, P, 1); if (lane == 0) ex = 0.0f;
        if (lane == 31) sZ[par][2 * wid + 4] = P;      // F_w slot

        // ---- two independent backward chains (zero block carries) ----
        #pragma unroll
        for (int k = 6; k >= 0; k--) {
            m[k]     = fmaf(cv[k],     m[k + 1], m[k]);
            m[8 + k] = fmaf(cv[8 + k], m[9 + k], m[8 + k]);
        }
        float Glo = m[0], Ghi = m[8];
        float P2 = fmaf(B8lo, fmaf(P8lo, gH0, Ghi), Glo);  // exact thread gm[0]

        // ---- backward warp scan (1 round), PRE-barrier ----
        v = __shfl_down_sync(0xffffffffu, P2, 1); P2 = fmaf(Mb0, v, P2);
        float ex2 = __shfl_down_sync(0xffffffffu, P2, 1); if (lane == 31) ex2 = 0.0f;
        if (lane == 0) sZ[par][2 * wid + 1] = P2;      // D_w slot

        float inl_nx = s_inlet[n + 2];
        bool need = s_need[n + 1] != 0;
        __syncthreads();

        // ---- post-barrier: ONE 64-bit LDS gives (C, Dm) ----
        float2 pr = *(const float2*)&sZ[par][2 * wid + 2];
        float C  = notfirst ? pr.x : 0.0f;    // F_{wid-1}
        float Dm = notlast  ? pr.y : 0.0f;    // D_{wid+1}
        float c   = fmaf(Qf,   C, ex);
        float cn1 = fmaf(QfD1, C, P);             // carry of thread t+1
        float Sa  = fmaf(Qb, Dm, ex2);
        float S   = fmaf(W1, cn1, Sa);

        // ---- exact block carries + apply (two independent streams) ----
        float cbh = fmaf(A8lo, c, P8lo);                    // fwd carry into hi
        float Sbl = fmaf(B8hi, S, fmaf(cbh, gH0, Ghi));     // back carry into lo
        #pragma unroll
        for (int k = 0; k < 8; k++) {
            m[k]     = fmaf(Lb[k],     Sbl, fmaf(c,   gl[k],     m[k]));
            m[8 + k] = fmaf(Lb[8 + k], S,   fmaf(cbh, gl[8 + k], m[8 + k]));
        }

        // ---- store row n+1 only if the interpolation will read it ----
        if (need) {
            float4* p = (float4*)row;
            p[0] = make_float4(m[0],  m[1],  m[2],  m[3]);
            p[1] = make_float4(m[4],  m[5],  m[6],  m[7]);
            p[2] = make_float4(m[8],  m[9],  m[10], m[11]);
            p[3] = make_float4(m[12], m[13], m[14], m[15]);
            if (tid == NTH - 1) row[NSYS - e0] = m[15];  // Neumann outlet copy
        }
        row += ROWP;
        inl = inl_nx;
    }
}

// ---------------------------------------------------------------------------
// Interpolation:  out[b] = (1-w) U[idx0] + w U[idx1]
// ---------------------------------------------------------------------------
__global__ void k_interp(const float* __restrict__ tq, float* __restrict__ out) {
    int b = blockIdx.x;
    float tn = tq[b] * g_par[2];
    float f = floorf(tn);
    int i0 = (int)f;
    i0 = max(0, min(i0, NT - 1));
    float w = tn - (float)i0;
    const float* r0 = g_U + (size_t)i0 * ROWP;
    const float* r1 = r0 + ROWP;
    float* o = out + (size_t)b * (NSYS + 1);
    for (int x = threadIdx.x; x <= NSYS; x += blockDim.x)
        o[x] = (1.0f - w) * r0[x] + w * r1[x];
}

// ---------------------------------------------------------------------------
extern "C" void kernel_launch(void* const* d_in, const int* in_sizes, int n_in,
                              void* d_out, int out_size) {
    const float* alpha = (const float*)d_in[0];
    const float* vel   = (const float*)d_in[1];
    const float* r0    = (const float*)d_in[2];
    const float* r1    = (const float*)d_in[3];
    const float* t     = (const float*)d_in[4];
    int B = in_sizes[4];

    k_main<<<1, NTH>>>(alpha, vel, r0, r1, t, B);
    k_interp<<<B, 256>>>(t, (float*)d_out);
}